// round 4
// baseline (speedup 1.0000x reference)
#include <cuda_runtime.h>
#include <cuda_bf16.h>

// Problem dims (fixed per reference)
#define BB   4
#define TT   2048
#define CC   1024
#define NH   16
#define HS   64
#define LL   256   // QL == KVL == 256

// ---------------- scratch (device globals; no runtime allocation) ----------------
__device__ float g_tmp1[LL * LL];            // W_uq^T @ W_uk          (256,256)
__device__ float g_M[CC * LL];               // W_dq^T @ tmp1          (1024,256)
__device__ float g_A[NH * LL * LL];          // per-head A_h           (16,256,256)
__device__ float g_V[LL * CC];               // W_uv^T @ W_o^T         (256,1024)
__device__ float g_cq[BB * TT * LL];         // x @ W_dq^T             (4,2048,256)
__device__ float g_qlat[(long long)BB * NH * TT * LL];   // (4,16,2048,256) 134MB
__device__ float g_ctx[(long long)BB * TT * NH * LL];    // (4,2048,16,256) 134MB

// ---------------- generic strided batched GEMM ----------------
// C[m,n] = sum_k A[m*sa_m + k*sa_k] * B[k*sb_k + n*sb_n]
// blockIdx.z decomposed as zb = z/zdiv, zh = z%zdiv; per-z base offsets applied.
__global__ void gemm_k(const float* __restrict__ A, const float* __restrict__ B,
                       float* __restrict__ C,
                       int M, int N, int K,
                       long long sa_m, long long sa_k,
                       long long sb_k, long long sb_n,
                       long long sc_m, long long sc_n,
                       int zdiv,
                       long long lAb, long long lAh,
                       long long lBb, long long lBh,
                       long long lCb, long long lCh)
{
    const int BM = 64, BN = 64, BK = 16;
    int z = blockIdx.z;
    int zb = z / zdiv, zh = z % zdiv;
    A += (long long)zb * lAb + (long long)zh * lAh;
    B += (long long)zb * lBb + (long long)zh * lBh;
    C += (long long)zb * lCb + (long long)zh * lCh;

    __shared__ float As[BK][BM];       // [k][m]
    __shared__ float Bs[BK][BN + 1];   // [k][n]

    int t  = threadIdx.x;        // 256 threads
    int tx = t % 16, ty = t / 16;
    int bm = blockIdx.y * BM, bn = blockIdx.x * BN;

    float acc[4][4] = {};

    for (int k0 = 0; k0 < K; k0 += BK) {
#pragma unroll
        for (int i = 0; i < 4; i++) {
            int e = t + i * 256;
            int kk = e / BM, m = e % BM;
            int gm = bm + m, gk = k0 + kk;
            As[kk][m] = (gm < M) ? A[(long long)gm * sa_m + (long long)gk * sa_k] : 0.f;
        }
#pragma unroll
        for (int i = 0; i < 4; i++) {
            int e = t + i * 256;
            int kk = e / BN, n = e % BN;
            int gn = bn + n, gk = k0 + kk;
            Bs[kk][n] = (gn < N) ? B[(long long)gk * sb_k + (long long)gn * sb_n] : 0.f;
        }
        __syncthreads();
#pragma unroll
        for (int kk = 0; kk < BK; kk++) {
            float a[4], b[4];
#pragma unroll
            for (int i = 0; i < 4; i++) a[i] = As[kk][ty * 4 + i];
#pragma unroll
            for (int j = 0; j < 4; j++) b[j] = Bs[kk][tx * 4 + j];
#pragma unroll
            for (int i = 0; i < 4; i++)
#pragma unroll
                for (int j = 0; j < 4; j++)
                    acc[i][j] = fmaf(a[i], b[j], acc[i][j]);
        }
        __syncthreads();
    }

#pragma unroll
    for (int i = 0; i < 4; i++) {
        int gm = bm + ty * 4 + i;
        if (gm >= M) continue;
#pragma unroll
        for (int j = 0; j < 4; j++) {
            int gn = bn + tx * 4 + j;
            if (gn < N)
                C[(long long)gm * sc_m + (long long)gn * sc_n] = acc[i][j];
        }
    }
}

// ---------------- flash attention over latent dim 256 ----------------
// grid = (T/64, NH, B), block = 256 threads
// Per block: 64 query rows; stream key blocks of 64 with online softmax.
#define QS_STRIDE 292   // 292 % 4 == 0 (float4-aligned rows), row byte-stride mod 128 = 16 -> 2-way worst
#define KS_STRIDE 292
#define SS_STRIDE 65

#define FA_SMEM_FLOATS (64 * QS_STRIDE + 64 * KS_STRIDE + 64 * SS_STRIDE + 3 * 64)
#define FA_SMEM_BYTES  (FA_SMEM_FLOATS * 4)

__global__ void flash_k(const float* __restrict__ qlat,
                        const float* __restrict__ ckv,
                        float* __restrict__ ctx)
{
    extern __shared__ float sh[];
    float* Qs   = sh;
    float* Ks   = Qs + 64 * QS_STRIDE;
    float* Ss   = Ks + 64 * KS_STRIDE;
    float* sm_m = Ss + 64 * SS_STRIDE;
    float* sm_l = sm_m + 64;
    float* sm_a = sm_l + 64;

    const int qb = blockIdx.x;   // 0..31
    const int h  = blockIdx.y;
    const int b  = blockIdx.z;
    const int t  = threadIdx.x;  // 0..255

    const float scale = 0.125f;  // 1/sqrt(64)

    // Load Q tile (64 x 256), pre-scaled
    const float* qptr = qlat + (((long long)b * NH + h) * TT + (long long)qb * 64) * LL;
#pragma unroll 4
    for (int i = 0; i < 64; i++)
        Qs[i * QS_STRIDE + t] = qptr[(long long)i * LL + t] * scale;

    if (t < 64) { sm_m[t] = -1e30f; sm_l[t] = 0.f; }

    float acc[64];
#pragma unroll
    for (int j = 0; j < 64; j++) acc[j] = 0.f;

    const int r_pv = t & 63;     // row this thread accumulates
    const int cg   = t >> 6;     // column group (64 cols each)

    const float* kbase = ckv + (long long)b * TT * LL;

    for (int nb = 0; nb <= qb; nb++) {
        __syncthreads();  // Qs ready (first iter) / prev PV done reading Ks
        // Load K block (64 x 256)
#pragma unroll 4
        for (int i = 0; i < 64; i++)
            Ks[i * KS_STRIDE + t] = kbase[((long long)nb * 64 + i) * LL + t];
        __syncthreads();

        // S = Q @ K^T  (register microtile 4x4, 16x16 threads; ty->cols, tx->rows)
        {
            int tx = t % 16, ty = t / 16;
            float s[4][4] = {};   // s[i][j]: i -> key col (ty), j -> query row (tx)
            for (int l = 0; l < 256; l += 4) {
                float4 a[4], bb[4];
#pragma unroll
                for (int i = 0; i < 4; i++)
                    a[i] = *reinterpret_cast<const float4*>(&Ks[(ty * 4 + i) * KS_STRIDE + l]);
#pragma unroll
                for (int j = 0; j < 4; j++)
                    bb[j] = *reinterpret_cast<const float4*>(&Qs[(tx * 4 + j) * QS_STRIDE + l]);
#pragma unroll
                for (int i = 0; i < 4; i++)
#pragma unroll
                    for (int j = 0; j < 4; j++) {
                        s[i][j] = fmaf(a[i].x, bb[j].x, s[i][j]);
                        s[i][j] = fmaf(a[i].y, bb[j].y, s[i][j]);
                        s[i][j] = fmaf(a[i].z, bb[j].z, s[i][j]);
                        s[i][j] = fmaf(a[i].w, bb[j].w, s[i][j]);
                    }
            }
            bool diag = (nb == qb);
#pragma unroll
            for (int i = 0; i < 4; i++) {
                int c = ty * 4 + i;
#pragma unroll
                for (int j = 0; j < 4; j++) {
                    int r = tx * 4 + j;
                    float v = s[i][j];
                    if (diag && c > r) v = -1e30f;   // causal mask on diagonal block
                    Ss[r * SS_STRIDE + c] = v;
                }
            }
        }
        __syncthreads();

        // Online softmax update (one thread per row)
        if (t < 64) {
            float mold = sm_m[t];
            float mnew = mold;
#pragma unroll 8
            for (int c = 0; c < 64; c++) mnew = fmaxf(mnew, Ss[t * SS_STRIDE + c]);
            float a = __expf(mold - mnew);
            float ssum = 0.f;
#pragma unroll 8
            for (int c = 0; c < 64; c++) {
                float p = __expf(Ss[t * SS_STRIDE + c] - mnew);
                Ss[t * SS_STRIDE + c] = p;
                ssum += p;
            }
            sm_a[t] = a;
            sm_m[t] = mnew;
            sm_l[t] = sm_l[t] * a + ssum;
        }
        __syncthreads();

        // acc = acc*alpha + P @ K
        {
            float a = sm_a[r_pv];
#pragma unroll
            for (int j = 0; j < 64; j++) acc[j] *= a;
            for (int c = 0; c < 64; c++) {
                float p = Ss[r_pv * SS_STRIDE + c];
                const float4* kr4 =
                    reinterpret_cast<const float4*>(&Ks[c * KS_STRIDE + cg * 64]);
#pragma unroll
                for (int j = 0; j < 16; j++) {
                    float4 kv = kr4[j];
                    acc[4 * j + 0] = fmaf(p, kv.x, acc[4 * j + 0]);
                    acc[4 * j + 1] = fmaf(p, kv.y, acc[4 * j + 1]);
                    acc[4 * j + 2] = fmaf(p, kv.z, acc[4 * j + 2]);
                    acc[4 * j + 3] = fmaf(p, kv.w, acc[4 * j + 3]);
                }
            }
        }
    }
    __syncthreads();

    // Write ctx[b, qb*64+r, h, cg*64 + j]
    float inv = 1.f / sm_l[r_pv];
    float* optr = ctx + ((((long long)b * TT + (long long)qb * 64 + r_pv) * NH + h) * LL) + cg * 64;
#pragma unroll
    for (int j = 0; j < 16; j++) {
        float4 v;
        v.x = acc[4 * j + 0] * inv;
        v.y = acc[4 * j + 1] * inv;
        v.z = acc[4 * j + 2] * inv;
        v.w = acc[4 * j + 3] * inv;
        reinterpret_cast<float4*>(optr)[j] = v;
    }
}

// ---------------- launch ----------------
extern "C" void kernel_launch(void* const* d_in, const int* in_sizes, int n_in,
                              void* d_out, int out_size)
{
    const float* x     = (const float*)d_in[0];   // (4,2048,1024)
    const float* W_dq  = (const float*)d_in[1];   // (256,1024)
    const float* W_uq  = (const float*)d_in[2];   // (1024,256)
    const float* W_dkv = (const float*)d_in[3];   // (256,1024)
    const float* W_uk  = (const float*)d_in[4];   // (1024,256)
    const float* W_uv  = (const float*)d_in[5];   // (1024,256)
    const float* W_o   = (const float*)d_in[6];   // (1024,1024)

    float* y   = (float*)d_out;                           // (4,2048,1024)
    float* ckv = y + (long long)BB * TT * CC;             // (4,2048,256)

    float *p_tmp1, *p_M, *p_A, *p_V, *p_cq, *p_qlat, *p_ctx;
    cudaGetSymbolAddress((void**)&p_tmp1, g_tmp1);
    cudaGetSymbolAddress((void**)&p_M,    g_M);
    cudaGetSymbolAddress((void**)&p_A,    g_A);
    cudaGetSymbolAddress((void**)&p_V,    g_V);
    cudaGetSymbolAddress((void**)&p_cq,   g_cq);
    cudaGetSymbolAddress((void**)&p_qlat, g_qlat);
    cudaGetSymbolAddress((void**)&p_ctx,  g_ctx);

    dim3 thr(256);

    // 1. tmp1 = W_uq^T @ W_uk              (256 x 256, K=1024)
    gemm_k<<<dim3(4, 4, 1), thr>>>(W_uq, W_uk, p_tmp1,
        256, 256, 1024, 1, 256, 256, 1, 256, 1,
        1, 0, 0, 0, 0, 0, 0);

    // 2. M = W_dq^T @ tmp1                 (1024 x 256, K=256)
    gemm_k<<<dim3(4, 16, 1), thr>>>(W_dq, p_tmp1, p_M,
        1024, 256, 256, 1, 1024, 256, 1, 256, 1,
        1, 0, 0, 0, 0, 0, 0);

    // 3. A_h = W_uq^T[:,hslice] @ k_eff[h] (16 x 256 x 256, K=64)
    gemm_k<<<dim3(4, 4, 16), thr>>>(W_uq, p_M, p_A,
        256, 256, 64, 1, 256, 256, 1, 256, 1,
        16, 0, 64 * 256, 0, 64 * 256, 0, 256 * 256);

    // 4. V = W_uv^T @ W_o^T                (256 x 1024, K=1024)
    gemm_k<<<dim3(16, 4, 1), thr>>>(W_uv, W_o, p_V,
        256, 1024, 1024, 1, 256, 1, 1024, 1024, 1,
        1, 0, 0, 0, 0, 0, 0);

    // 5. cq[b] = x[b] @ W_dq^T             (4 x 2048 x 256, K=1024)
    gemm_k<<<dim3(4, 32, 4), thr>>>(x, W_dq, p_cq,
        2048, 256, 1024, 1024, 1, 1, 1024, 256, 1,
        1, (long long)TT * CC, 0, 0, 0, (long long)TT * LL, 0);

    // 6. c_kv[b] = x[b] @ W_dkv^T          -> second output region
    gemm_k<<<dim3(4, 32, 4), thr>>>(x, W_dkv, ckv,
        2048, 256, 1024, 1024, 1, 1, 1024, 256, 1,
        1, (long long)TT * CC, 0, 0, 0, (long long)TT * LL, 0);

    // 7. qlat[b,h] = cq[b] @ A_h           (64 x 2048 x 256, K=256)
    gemm_k<<<dim3(4, 32, 64), thr>>>(p_cq, p_A, p_qlat,
        2048, 256, 256, 256, 1, 256, 1, 256, 1,
        16, (long long)TT * LL, 0, 0, 256 * 256,
        (long long)NH * TT * LL, (long long)TT * LL);

    // 8. flash attention -> ctx (B, T, NH, L)
    cudaFuncSetAttribute(flash_k, cudaFuncAttributeMaxDynamicSharedMemorySize, FA_SMEM_BYTES);
    flash_k<<<dim3(TT / 64, NH, BB), thr, FA_SMEM_BYTES>>>(p_qlat, ckv, p_ctx);

    // 9. y[b,:,hslice] = ctx[b,:,h,:] @ V[:,hslice]   (64 x 2048 x 64, K=256)
    gemm_k<<<dim3(1, 32, 64), thr>>>(p_ctx, p_V, y,
        2048, 64, 256, (long long)NH * LL, 1, CC, 1, CC, 1,
        16, (long long)TT * NH * LL, LL, 0, HS,
        (long long)TT * CC, HS);
}

// round 6
// speedup vs baseline: 5.0651x; 5.0651x over previous
#include <cuda_runtime.h>
#include <cuda_bf16.h>
#include <cstdint>

// Problem dims (fixed per reference)
#define BB   4
#define TT   2048
#define CC   1024
#define NH   16
#define HS   64
#define LL   256

// ---------------- scratch (device globals; no runtime allocation) ----------------
__device__ float g_tmp1[LL * LL];            // W_uq^T @ W_uk          (256,256)
__device__ float g_M[CC * LL];               // W_dq^T @ tmp1          (1024,256)
__device__ float g_At[NH * LL * LL];         // A_h^T  [h][n][k]       (16,256,256)
__device__ float g_Vt[CC * LL];              // V^T    [d][l]          (1024,256)
__device__ float g_cq[BB * TT * LL];         // x @ W_dq^T             (8192,256)
__device__ float g_qlat[(long long)BB * NH * TT * LL];   // (4,16,2048,256)
__device__ float g_ctx[(long long)BB * TT * NH * LL];    // (4,2048,16,256)

// ---------------- tf32 helpers ----------------
__device__ __forceinline__ float f2tff(float x) {
    uint32_t r;
    asm("cvt.rna.tf32.f32 %0, %1;" : "=r"(r) : "f"(x));
    return __uint_as_float(r);
}

__device__ __forceinline__ void mma_tf32(float* d, const uint32_t* a, const uint32_t* b) {
    asm volatile(
        "mma.sync.aligned.m16n8k8.row.col.f32.tf32.tf32.f32 "
        "{%0,%1,%2,%3},{%4,%5,%6,%7},{%8,%9},{%0,%1,%2,%3};\n"
        : "+f"(d[0]), "+f"(d[1]), "+f"(d[2]), "+f"(d[3])
        : "r"(a[0]), "r"(a[1]), "r"(a[2]), "r"(a[3]), "r"(b[0]), "r"(b[1]));
}

// ---------------- generic TF32 GEMM ----------------
// C[m,n] = sum_k A[m*sa_m + k*sa_k] * B[n*sb_n + k*sb_k]   (B given k-major per column n)
// BM=128, BK=16, 256 threads (8 warps: 4 x 2). Warp tile: 32 x (BN/2).
// Requires M%128==0, N%BN==0, K%16==0 (true for all call sites).
template<int BN>
__global__ void __launch_bounds__(256)
gemm_tf32(const float* __restrict__ A, const float* __restrict__ B, float* __restrict__ C,
          int M, int N, int K,
          long long sa_m, long long sa_k,
          long long sb_n, long long sb_k,
          long long sc_m,
          int zdiv,
          long long lAb, long long lAh,
          long long lBb, long long lBh,
          long long lCb, long long lCh)
{
    const int BM = 128, BK = 16, SA = 20, SB = 20;
    const int WN = BN / 2;      // warp tile n-width
    const int NT = WN / 8;      // n8 tiles per warp
    const int RBS = (BN * BK) / 256;   // scalar B elems / thread
    const int RBV = RBS / 4;           // float4 B loads / thread

    __shared__ float As[2][BM * SA];
    __shared__ float Bs[2][BN * SB];

    int z = blockIdx.z, zb = z / zdiv, zh = z % zdiv;
    A += (long long)zb * lAb + (long long)zh * lAh;
    B += (long long)zb * lBb + (long long)zh * lBh;
    C += (long long)zb * lCb + (long long)zh * lCh;

    const int t = threadIdx.x, lane = t & 31, wid = t >> 5;
    const int warp_m = wid & 3, warp_n = wid >> 2;
    const int rg = lane >> 2;          // groupID (fragment row)
    const int tg = lane & 3;           // threadID-in-group (fragment col)
    const long long bm = (long long)blockIdx.y * BM;
    const long long bn = (long long)blockIdx.x * BN;

    const bool vecA = (sa_k == 1), vecB = (sb_k == 1);
    const int nk = K / BK;

    float acc[2][NT][4];
#pragma unroll
    for (int mt = 0; mt < 2; mt++)
#pragma unroll
        for (int nt = 0; nt < NT; nt++)
#pragma unroll
            for (int j = 0; j < 4; j++) acc[mt][nt][j] = 0.f;

    float ra[8], rb[RBS];

    auto loadA = [&](int kt) {
        long long k0 = (long long)kt * BK;
        if (vecA) {
#pragma unroll
            for (int i = 0; i < 2; i++) {
                int f = t + i * 256;
                int row = f >> 2, c4 = (f & 3) * 4;
                float4 v = *reinterpret_cast<const float4*>(&A[(bm + row) * sa_m + k0 + c4]);
                ra[i * 4 + 0] = v.x; ra[i * 4 + 1] = v.y;
                ra[i * 4 + 2] = v.z; ra[i * 4 + 3] = v.w;
            }
        } else {
#pragma unroll
            for (int i = 0; i < 8; i++) {
                int e = t + i * 256;
                int kk = e >> 7, row = e & 127;
                ra[i] = A[(bm + row) * sa_m + (k0 + kk) * sa_k];
            }
        }
    };
    auto storeA = [&](int buf) {
        if (vecA) {
#pragma unroll
            for (int i = 0; i < 2; i++) {
                int f = t + i * 256;
                int row = f >> 2, c4 = (f & 3) * 4;
                float* d = &As[buf][row * SA + c4];
#pragma unroll
                for (int j = 0; j < 4; j++) d[j] = f2tff(ra[i * 4 + j]);
            }
        } else {
#pragma unroll
            for (int i = 0; i < 8; i++) {
                int e = t + i * 256;
                int kk = e >> 7, row = e & 127;
                As[buf][row * SA + kk] = f2tff(ra[i]);
            }
        }
    };
    auto loadB = [&](int kt) {
        long long k0 = (long long)kt * BK;
        if (vecB) {
#pragma unroll
            for (int i = 0; i < RBV; i++) {
                int f = t + i * 256;
                int row = f >> 2, c4 = (f & 3) * 4;
                float4 v = *reinterpret_cast<const float4*>(&B[(bn + row) * sb_n + k0 + c4]);
                rb[i * 4 + 0] = v.x; rb[i * 4 + 1] = v.y;
                rb[i * 4 + 2] = v.z; rb[i * 4 + 3] = v.w;
            }
        } else {
#pragma unroll
            for (int i = 0; i < RBS; i++) {
                int e = t + i * 256;
                int kk = e / BN, n = e % BN;
                rb[i] = B[(bn + n) * sb_n + (k0 + kk) * sb_k];
            }
        }
    };
    auto storeB = [&](int buf) {
        if (vecB) {
#pragma unroll
            for (int i = 0; i < RBV; i++) {
                int f = t + i * 256;
                int row = f >> 2, c4 = (f & 3) * 4;
                float* d = &Bs[buf][row * SB + c4];
#pragma unroll
                for (int j = 0; j < 4; j++) d[j] = f2tff(rb[i * 4 + j]);
            }
        } else {
#pragma unroll
            for (int i = 0; i < RBS; i++) {
                int e = t + i * 256;
                int kk = e / BN, n = e % BN;
                Bs[buf][n * SB + kk] = f2tff(rb[i]);
            }
        }
    };

    auto compute = [&](int buf) {
#pragma unroll
        for (int ks = 0; ks < 2; ks++) {
            uint32_t af[2][4];
            const int ar = warp_m * 32 + rg;
            const int ac = ks * 8 + tg;
#pragma unroll
            for (int mt = 0; mt < 2; mt++) {
                const float* p = &As[buf][(ar + mt * 16) * SA + ac];
                af[mt][0] = __float_as_uint(p[0]);
                af[mt][1] = __float_as_uint(p[8 * SA]);
                af[mt][2] = __float_as_uint(p[4]);
                af[mt][3] = __float_as_uint(p[8 * SA + 4]);
            }
            uint32_t bf[NT][2];
            const int br = warp_n * WN + rg;
            const int bc = ks * 8 + tg;
#pragma unroll
            for (int nt = 0; nt < NT; nt++) {
                const float* p = &Bs[buf][(br + nt * 8) * SB + bc];
                bf[nt][0] = __float_as_uint(p[0]);
                bf[nt][1] = __float_as_uint(p[4]);
            }
#pragma unroll
            for (int mt = 0; mt < 2; mt++)
#pragma unroll
                for (int nt = 0; nt < NT; nt++)
                    mma_tf32(acc[mt][nt], af[mt], bf[nt]);
        }
    };

    loadA(0); loadB(0);
    storeA(0); storeB(0);
    __syncthreads();

    for (int kt = 0; kt < nk; kt++) {
        int buf = kt & 1;
        bool nxt = (kt + 1 < nk);
        if (nxt) { loadA(kt + 1); loadB(kt + 1); }
        compute(buf);
        if (nxt) { storeA(buf ^ 1); storeB(buf ^ 1); }
        __syncthreads();
    }

    // epilogue
#pragma unroll
    for (int mt = 0; mt < 2; mt++) {
        long long gm0 = bm + warp_m * 32 + mt * 16 + rg;
#pragma unroll
        for (int nt = 0; nt < NT; nt++) {
            long long gn = bn + warp_n * WN + nt * 8 + tg * 2;
            float2 v0 = make_float2(acc[mt][nt][0], acc[mt][nt][1]);
            float2 v1 = make_float2(acc[mt][nt][2], acc[mt][nt][3]);
            *reinterpret_cast<float2*>(&C[gm0 * sc_m + gn]) = v0;
            *reinterpret_cast<float2*>(&C[(gm0 + 8) * sc_m + gn]) = v1;
        }
    }
}

// ---------------- TF32 flash attention over latent dim 256 ----------------
// grid = (T/64, NH, B), 256 threads (8 warps: 4 x 2).
// S warp tile: 16 x 32 (over 64x64 scores). PV warp tile: 16 x 128 (over 64x256 out).
#define QK_S 268   // row stride for Q/K tiles: (lane/4)*268 and k*268 patterns conflict-free
#define SS_S 76    // row stride for P tile

#define FA_SMEM_BYTES ((2 * 64 * QK_S + 64 * SS_S + 3 * 64) * 4)

__global__ void __launch_bounds__(256)
flash_tf32(const float* __restrict__ qlat, const float* __restrict__ ckv,
           float* __restrict__ ctx)
{
    extern __shared__ float sh[];
    float* Qs   = sh;                 // 64 x QK_S
    float* Ks   = Qs + 64 * QK_S;     // 64 x QK_S
    float* Ss   = Ks + 64 * QK_S;     // 64 x SS_S
    float* sm_m = Ss + 64 * SS_S;
    float* sm_l = sm_m + 64;
    float* sm_a = sm_l + 64;

    const int qb = blockIdx.x, h = blockIdx.y, b = blockIdx.z;
    const int t = threadIdx.x, lane = t & 31, wid = t >> 5;
    const int warp_m = wid & 3, warp_n = wid >> 2;
    const int rg = lane >> 2;      // fragment row in group
    const int tg = lane & 3;       // fragment col in group

    // Load Q tile (64 x 256), pre-scaled by 1/sqrt(hs)=0.125, tf32-rounded
    const float* qptr = qlat + (((long long)b * NH + h) * TT + (long long)qb * 64) * LL;
#pragma unroll
    for (int i = 0; i < 16; i++) {
        int f = t + i * 256;
        int row = f >> 6, c = (f & 63) * 4;
        float4 v = *reinterpret_cast<const float4*>(&qptr[(long long)row * LL + c]);
        float* d = &Qs[row * QK_S + c];
        d[0] = f2tff(v.x * 0.125f); d[1] = f2tff(v.y * 0.125f);
        d[2] = f2tff(v.z * 0.125f); d[3] = f2tff(v.w * 0.125f);
    }
    if (t < 64) { sm_m[t] = -1e30f; sm_l[t] = 0.f; }

    float acc[16][4];
#pragma unroll
    for (int nt = 0; nt < 16; nt++)
#pragma unroll
        for (int j = 0; j < 4; j++) acc[nt][j] = 0.f;

    const float* kbase = ckv + (long long)b * TT * LL;

    for (int nb = 0; nb <= qb; nb++) {
        __syncthreads();   // prev PV done reading Ks/Ss; Q loads visible on first iter
        // Stage K block (64 keys x 256 latent), tf32-rounded
#pragma unroll
        for (int i = 0; i < 16; i++) {
            int f = t + i * 256;
            int row = f >> 6, c = (f & 63) * 4;
            float4 v = *reinterpret_cast<const float4*>(
                &kbase[((long long)nb * 64 + row) * LL + c]);
            float* d = &Ks[row * QK_S + c];
            d[0] = f2tff(v.x); d[1] = f2tff(v.y); d[2] = f2tff(v.z); d[3] = f2tff(v.w);
        }
        __syncthreads();

        // ---- S = Q @ K^T (warp tile 16 x 32, K=256) ----
        float sacc[4][4];
#pragma unroll
        for (int nt = 0; nt < 4; nt++)
#pragma unroll
            for (int j = 0; j < 4; j++) sacc[nt][j] = 0.f;

#pragma unroll 4
        for (int ks = 0; ks < 32; ks++) {
            uint32_t af[4];
            const float* pa = &Qs[(warp_m * 16 + rg) * QK_S + ks * 8 + tg];
            af[0] = __float_as_uint(pa[0]);
            af[1] = __float_as_uint(pa[8 * QK_S]);
            af[2] = __float_as_uint(pa[4]);
            af[3] = __float_as_uint(pa[8 * QK_S + 4]);
#pragma unroll
            for (int nt = 0; nt < 4; nt++) {
                const float* pb = &Ks[(warp_n * 32 + nt * 8 + rg) * QK_S + ks * 8 + tg];
                uint32_t bf[2] = { __float_as_uint(pb[0]), __float_as_uint(pb[4]) };
                mma_tf32(sacc[nt], af, bf);
            }
        }

        // write S to smem with causal mask on the diagonal block
        const bool diag = (nb == qb);
#pragma unroll
        for (int nt = 0; nt < 4; nt++) {
            int colb = warp_n * 32 + nt * 8 + tg * 2;
#pragma unroll
            for (int half = 0; half < 2; half++) {
                int row = warp_m * 16 + rg + half * 8;
                float v0 = sacc[nt][half * 2 + 0];
                float v1 = sacc[nt][half * 2 + 1];
                if (diag) {
                    if (colb     > row) v0 = -1e30f;
                    if (colb + 1 > row) v1 = -1e30f;
                }
                Ss[row * SS_S + colb]     = v0;
                Ss[row * SS_S + colb + 1] = v1;
            }
        }
        __syncthreads();

        // ---- online softmax (4 threads per row) ----
        {
            int row = t >> 2, q = t & 3;
            float* srow = &Ss[row * SS_S + q * 16];
            float m = -1e30f;
#pragma unroll
            for (int j = 0; j < 16; j++) m = fmaxf(m, srow[j]);
            m = fmaxf(m, __shfl_xor_sync(0xffffffffu, m, 1));
            m = fmaxf(m, __shfl_xor_sync(0xffffffffu, m, 2));
            float mold = sm_m[row];
            float mnew = fmaxf(m, mold);
            float ssum = 0.f;
#pragma unroll
            for (int j = 0; j < 16; j++) {
                float p = __expf(srow[j] - mnew);
                srow[j] = f2tff(p);
                ssum += p;
            }
            ssum += __shfl_xor_sync(0xffffffffu, ssum, 1);
            ssum += __shfl_xor_sync(0xffffffffu, ssum, 2);
            if (q == 0) {
                float alpha = __expf(mold - mnew);
                sm_a[row] = alpha;
                sm_l[row] = sm_l[row] * alpha + ssum;
                sm_m[row] = mnew;
            }
        }
        __syncthreads();

        // ---- rescale + PV: O(16x128 per warp) += P(16x64) @ K(64x256 slice) ----
        {
            int r0 = warp_m * 16 + rg;
            float a0 = sm_a[r0], a1 = sm_a[r0 + 8];
#pragma unroll
            for (int nt = 0; nt < 16; nt++) {
                acc[nt][0] *= a0; acc[nt][1] *= a0;
                acc[nt][2] *= a1; acc[nt][3] *= a1;
            }
#pragma unroll
            for (int ks = 0; ks < 8; ks++) {
                uint32_t af[4];
                const float* pa = &Ss[(warp_m * 16 + rg) * SS_S + ks * 8 + tg];
                af[0] = __float_as_uint(pa[0]);
                af[1] = __float_as_uint(pa[8 * SS_S]);
                af[2] = __float_as_uint(pa[4]);
                af[3] = __float_as_uint(pa[8 * SS_S + 4]);
#pragma unroll
                for (int nt = 0; nt < 16; nt++) {
                    int n = warp_n * 128 + nt * 8 + rg;
                    const float* pb = &Ks[(ks * 8 + tg) * QK_S + n];
                    uint32_t bf[2] = { __float_as_uint(pb[0]),
                                       __float_as_uint(pb[4 * QK_S]) };
                    mma_tf32(acc[nt], af, bf);
                }
            }
        }
    }

    // ---- epilogue: normalize and write ctx[b, t, h, l] ----
    {
        int r0 = warp_m * 16 + rg;
        float il0 = 1.f / sm_l[r0], il1 = 1.f / sm_l[r0 + 8];
        float* obase = ctx + (((long long)b * TT + (long long)qb * 64) * NH + h) * (long long)LL;
#pragma unroll
        for (int nt = 0; nt < 16; nt++) {
            int col = warp_n * 128 + nt * 8 + tg * 2;
            float2 v0 = make_float2(acc[nt][0] * il0, acc[nt][1] * il0);
            float2 v1 = make_float2(acc[nt][2] * il1, acc[nt][3] * il1);
            *reinterpret_cast<float2*>(&obase[(long long)r0 * (NH * LL) + col]) = v0;
            *reinterpret_cast<float2*>(&obase[(long long)(r0 + 8) * (NH * LL) + col]) = v1;
        }
    }
}

// ---------------- launch ----------------
extern "C" void kernel_launch(void* const* d_in, const int* in_sizes, int n_in,
                              void* d_out, int out_size)
{
    const float* x     = (const float*)d_in[0];   // (4,2048,1024)
    const float* W_dq  = (const float*)d_in[1];   // (256,1024)
    const float* W_uq  = (const float*)d_in[2];   // (1024,256)
    const float* W_dkv = (const float*)d_in[3];   // (256,1024)
    const float* W_uk  = (const float*)d_in[4];   // (1024,256)
    const float* W_uv  = (const float*)d_in[5];   // (1024,256)
    const float* W_o   = (const float*)d_in[6];   // (1024,1024)

    float* y   = (float*)d_out;                    // (4,2048,1024)
    float* ckv = y + (long long)BB * TT * CC;      // (4,2048,256)

    float *p_tmp1, *p_M, *p_At, *p_Vt, *p_cq, *p_qlat, *p_ctx;
    cudaGetSymbolAddress((void**)&p_tmp1, g_tmp1);
    cudaGetSymbolAddress((void**)&p_M,    g_M);
    cudaGetSymbolAddress((void**)&p_At,   g_At);
    cudaGetSymbolAddress((void**)&p_Vt,   g_Vt);
    cudaGetSymbolAddress((void**)&p_cq,   g_cq);
    cudaGetSymbolAddress((void**)&p_qlat, g_qlat);
    cudaGetSymbolAddress((void**)&p_ctx,  g_ctx);

    dim3 thr(256);

    // 1. tmp1[i,j] = sum_c W_uq[c,i] * W_uk[c,j]     (256 x 256, K=1024)
    gemm_tf32<128><<<dim3(2, 2, 1), thr>>>(W_uq, W_uk, p_tmp1,
        256, 256, 1024,  1, 256,  1, 256,  256,
        1, 0, 0, 0, 0, 0, 0);

    // 2. M_[c,j] = sum_i W_dq[i,c] * tmp1[i,j]       (1024 x 256, K=256)
    gemm_tf32<128><<<dim3(2, 8, 1), thr>>>(W_dq, p_tmp1, p_M,
        1024, 256, 256,  1, 1024,  1, 256,  256,
        1, 0, 0, 0, 0, 0, 0);

    // 3. At_h[n,m] = sum_k M_[h*64+k, n] * W_uq[h*64+k, m]   (16 x 256 x 256, K=64)
    gemm_tf32<128><<<dim3(2, 2, 16), thr>>>(p_M, W_uq, p_At,
        256, 256, 64,  1, 256,  1, 256,  256,
        16, 0, 64 * 256, 0, 64 * 256, 0, 256 * 256);

    // 4. Vt[d,l] = sum_c W_o[d,c] * W_uv[c,l]        (1024 x 256, K=1024)
    gemm_tf32<128><<<dim3(2, 8, 1), thr>>>(W_o, W_uv, p_Vt,
        1024, 256, 1024,  1024, 1,  1, 256,  256,
        1, 0, 0, 0, 0, 0, 0);

    // 5. cq = x @ W_dq^T                             (8192 x 256, K=1024)
    gemm_tf32<128><<<dim3(2, 64, 1), thr>>>(x, W_dq, p_cq,
        8192, 256, 1024,  1024, 1,  1024, 1,  256,
        1, 0, 0, 0, 0, 0, 0);

    // 6. c_kv = x @ W_dkv^T -> second output region
    gemm_tf32<128><<<dim3(2, 64, 1), thr>>>(x, W_dkv, ckv,
        8192, 256, 1024,  1024, 1,  1024, 1,  256,
        1, 0, 0, 0, 0, 0, 0);

    // 7. qlat[b,h] = cq[b] @ At_h^T                  (64 x 2048 x 256, K=256)
    gemm_tf32<128><<<dim3(2, 16, 64), thr>>>(p_cq, p_At, p_qlat,
        2048, 256, 256,  256, 1,  256, 1,  256,
        16, (long long)TT * LL, 0, 0, 256 * 256,
        (long long)NH * TT * LL, (long long)TT * LL);

    // 8. flash attention -> ctx (B, T, NH, L)
    cudaFuncSetAttribute(flash_tf32, cudaFuncAttributeMaxDynamicSharedMemorySize,
                         FA_SMEM_BYTES);
    flash_tf32<<<dim3(TT / 64, NH, BB), thr, FA_SMEM_BYTES>>>(p_qlat, ckv, p_ctx);

    // 9. y[b,:,h*64:+64] = ctx[b,:,h,:] @ Vt[h*64:+64,:]^T  (64 x 2048 x 64, K=256)
    gemm_tf32<64><<<dim3(1, 16, 64), thr>>>(p_ctx, p_Vt, y,
        2048, 64, 256,  NH * LL, 1,  256, 1,  CC,
        16, (long long)TT * NH * LL, LL, 0, 64 * 256,
        (long long)TT * CC, 64);
}

// round 10
// speedup vs baseline: 12.0141x; 2.3719x over previous
#include <cuda_runtime.h>
#include <cuda_bf16.h>
#include <cstdint>

// Problem dims (fixed per reference)
#define BB   4
#define TT   2048
#define CC   1024
#define NH   16
#define HS   64
#define LL   256

// ---------------- scratch (device globals; no runtime allocation) ----------------
__device__ float g_tmp1[LL * LL];            // W_uq^T @ W_uk            (256,256)
__device__ float g_M[CC * LL];               // W_dq^T @ tmp1 (k_eff)    (1024,256)
__device__ float g_Vt[CC * LL];              // W_o @ W_uv  (v_eff^T)    (1024,256)
__device__ float g_cq[BB * TT * LL];         // x @ W_dq^T               (8192,256)
__device__ float g_q [(long long)BB * NH * TT * HS];   // per-head q     (4,16,2048,64)
__device__ float g_kk[(long long)BB * NH * TT * HS];   // ckv @ k_eff^T  (4,16,2048,64)
__device__ float g_vv[(long long)BB * NH * TT * HS];   // ckv @ v_eff    (4,16,2048,64)

// ---------------- tf32 helpers ----------------
__device__ __forceinline__ float f2tff(float x) {
    uint32_t r;
    asm("cvt.rna.tf32.f32 %0, %1;" : "=r"(r) : "f"(x));
    return __uint_as_float(r);
}

__device__ __forceinline__ void mma_tf32(float* d, const uint32_t* a, const uint32_t* b) {
    asm volatile(
        "mma.sync.aligned.m16n8k8.row.col.f32.tf32.tf32.f32 "
        "{%0,%1,%2,%3},{%4,%5,%6,%7},{%8,%9},{%0,%1,%2,%3};\n"
        : "+f"(d[0]), "+f"(d[1]), "+f"(d[2]), "+f"(d[3])
        : "r"(a[0]), "r"(a[1]), "r"(a[2]), "r"(a[3]), "r"(b[0]), "r"(b[1]));
}

// ---------------- generic TF32 GEMM ----------------
// C[m,n] = sum_k A[m*sa_m + k*sa_k] * B[n*sb_n + k*sb_k]
// BM=128, BK=16, 256 threads (8 warps: 4 x 2). Warp tile: 32 x (BN/2).
// Requires M%128==0, N%BN==0, K%16==0 (true for all call sites).
template<int BN>
__global__ void __launch_bounds__(256)
gemm_tf32(const float* __restrict__ A, const float* __restrict__ B, float* __restrict__ C,
          int M, int N, int K,
          long long sa_m, long long sa_k,
          long long sb_n, long long sb_k,
          long long sc_m,
          int zdiv,
          long long lAb, long long lAh,
          long long lBb, long long lBh,
          long long lCb, long long lCh)
{
    const int BM = 128, BK = 16, SA = 20, SB = 20;
    const int WN = BN / 2;
    const int NT = WN / 8;
    const int RBS = (BN * BK) / 256;
    const int RBV = RBS / 4;

    __shared__ float As[2][BM * SA];
    __shared__ float Bs[2][BN * SB];

    int z = blockIdx.z, zb = z / zdiv, zh = z % zdiv;
    A += (long long)zb * lAb + (long long)zh * lAh;
    B += (long long)zb * lBb + (long long)zh * lBh;
    C += (long long)zb * lCb + (long long)zh * lCh;

    const int t = threadIdx.x, lane = t & 31, wid = t >> 5;
    const int warp_m = wid & 3, warp_n = wid >> 2;
    const int rg = lane >> 2;
    const int tg = lane & 3;
    const long long bm = (long long)blockIdx.y * BM;
    const long long bn = (long long)blockIdx.x * BN;

    const bool vecA = (sa_k == 1), vecB = (sb_k == 1);
    const int nk = K / BK;

    float acc[2][NT][4];
#pragma unroll
    for (int mt = 0; mt < 2; mt++)
#pragma unroll
        for (int nt = 0; nt < NT; nt++)
#pragma unroll
            for (int j = 0; j < 4; j++) acc[mt][nt][j] = 0.f;

    float ra[8], rb[RBS];

    auto loadA = [&](int kt) {
        long long k0 = (long long)kt * BK;
        if (vecA) {
#pragma unroll
            for (int i = 0; i < 2; i++) {
                int f = t + i * 256;
                int row = f >> 2, c4 = (f & 3) * 4;
                float4 v = *reinterpret_cast<const float4*>(&A[(bm + row) * sa_m + k0 + c4]);
                ra[i * 4 + 0] = v.x; ra[i * 4 + 1] = v.y;
                ra[i * 4 + 2] = v.z; ra[i * 4 + 3] = v.w;
            }
        } else {
#pragma unroll
            for (int i = 0; i < 8; i++) {
                int e = t + i * 256;
                int kk = e >> 7, row = e & 127;
                ra[i] = A[(bm + row) * sa_m + (k0 + kk) * sa_k];
            }
        }
    };
    auto storeA = [&](int buf) {
        if (vecA) {
#pragma unroll
            for (int i = 0; i < 2; i++) {
                int f = t + i * 256;
                int row = f >> 2, c4 = (f & 3) * 4;
                float* d = &As[buf][row * SA + c4];
#pragma unroll
                for (int j = 0; j < 4; j++) d[j] = f2tff(ra[i * 4 + j]);
            }
        } else {
#pragma unroll
            for (int i = 0; i < 8; i++) {
                int e = t + i * 256;
                int kk = e >> 7, row = e & 127;
                As[buf][row * SA + kk] = f2tff(ra[i]);
            }
        }
    };
    auto loadB = [&](int kt) {
        long long k0 = (long long)kt * BK;
        if (vecB) {
#pragma unroll
            for (int i = 0; i < RBV; i++) {
                int f = t + i * 256;
                int row = f >> 2, c4 = (f & 3) * 4;
                float4 v = *reinterpret_cast<const float4*>(&B[(bn + row) * sb_n + k0 + c4]);
                rb[i * 4 + 0] = v.x; rb[i * 4 + 1] = v.y;
                rb[i * 4 + 2] = v.z; rb[i * 4 + 3] = v.w;
            }
        } else {
#pragma unroll
            for (int i = 0; i < RBS; i++) {
                int e = t + i * 256;
                int kk = e / BN, n = e % BN;
                rb[i] = B[(bn + n) * sb_n + (k0 + kk) * sb_k];
            }
        }
    };
    auto storeB = [&](int buf) {
        if (vecB) {
#pragma unroll
            for (int i = 0; i < RBV; i++) {
                int f = t + i * 256;
                int row = f >> 2, c4 = (f & 3) * 4;
                float* d = &Bs[buf][row * SB + c4];
#pragma unroll
                for (int j = 0; j < 4; j++) d[j] = f2tff(rb[i * 4 + j]);
            }
        } else {
#pragma unroll
            for (int i = 0; i < RBS; i++) {
                int e = t + i * 256;
                int kk = e / BN, n = e % BN;
                Bs[buf][n * SB + kk] = f2tff(rb[i]);
            }
        }
    };

    auto compute = [&](int buf) {
#pragma unroll
        for (int ks = 0; ks < 2; ks++) {
            uint32_t af[2][4];
            const int ar = warp_m * 32 + rg;
            const int ac = ks * 8 + tg;
#pragma unroll
            for (int mt = 0; mt < 2; mt++) {
                const float* p = &As[buf][(ar + mt * 16) * SA + ac];
                af[mt][0] = __float_as_uint(p[0]);
                af[mt][1] = __float_as_uint(p[8 * SA]);
                af[mt][2] = __float_as_uint(p[4]);
                af[mt][3] = __float_as_uint(p[8 * SA + 4]);
            }
            uint32_t bf[NT][2];
            const int br = warp_n * WN + rg;
            const int bc = ks * 8 + tg;
#pragma unroll
            for (int nt = 0; nt < NT; nt++) {
                const float* p = &Bs[buf][(br + nt * 8) * SB + bc];
                bf[nt][0] = __float_as_uint(p[0]);
                bf[nt][1] = __float_as_uint(p[4]);
            }
#pragma unroll
            for (int mt = 0; mt < 2; mt++)
#pragma unroll
                for (int nt = 0; nt < NT; nt++)
                    mma_tf32(acc[mt][nt], af[mt], bf[nt]);
        }
    };

    loadA(0); loadB(0);
    storeA(0); storeB(0);
    __syncthreads();

    for (int kt = 0; kt < nk; kt++) {
        int buf = kt & 1;
        bool nxt = (kt + 1 < nk);
        if (nxt) { loadA(kt + 1); loadB(kt + 1); }
        compute(buf);
        if (nxt) { storeA(buf ^ 1); storeB(buf ^ 1); }
        __syncthreads();
    }

#pragma unroll
    for (int mt = 0; mt < 2; mt++) {
        long long gm0 = bm + warp_m * 32 + mt * 16 + rg;
#pragma unroll
        for (int nt = 0; nt < NT; nt++) {
            long long gn = bn + warp_n * WN + nt * 8 + tg * 2;
            float2 v0 = make_float2(acc[mt][nt][0], acc[mt][nt][1]);
            float2 v1 = make_float2(acc[mt][nt][2], acc[mt][nt][3]);
            *reinterpret_cast<float2*>(&C[gm0 * sc_m + gn]) = v0;
            *reinterpret_cast<float2*>(&C[(gm0 + 8) * sc_m + gn]) = v1;
        }
    }
}

// ---------------- TF32 flash attention, hs = 64 ----------------
// grid = (T/128, NH, B), 256 threads (8 warps). Warp w owns rows 16w..16w+15
// of the 128-row Q tile end-to-end: S mma -> register softmax (quad shuffles)
// -> P via smem -> PV mma. Only 2 block-wide syncs per key block (K/V staging).
#define SQ 68   // Q row stride:  row-major fragment reads conflict-free (68%32=4)
#define SK 68   // K row stride
#define SV 72   // V row stride:  k-major fragment reads conflict-free (72%32=8)
#define SP 68   // P row stride

#define FA2_SMEM_BYTES ((128 * SQ + 64 * SK + 64 * SV + 128 * SP) * 4)

__global__ void __launch_bounds__(256)
flash2(const float* __restrict__ qg, const float* __restrict__ kg,
       const float* __restrict__ vg, float* __restrict__ y)
{
    extern __shared__ float sh[];
    float* Qs = sh;               // 128 x SQ
    float* Ks = Qs + 128 * SQ;    // 64 x SK
    float* Vs = Ks + 64 * SK;     // 64 x SV
    float* Ps = Vs + 64 * SV;     // 128 x SP

    const int qb = (int)gridDim.x - 1 - (int)blockIdx.x;  // heavy blocks first
    const int h = blockIdx.y, b = blockIdx.z;
    const int t = threadIdx.x, lane = t & 31, w = t >> 5;
    const int rg = lane >> 2, tg = lane & 3;
    const int q0 = qb * 128;

    const long long bh = (long long)(b * NH + h) * TT;

    // stage Q (128 x 64), pre-scaled by 1/sqrt(hs)
    const float* qptr = qg + (bh + q0) * HS;
#pragma unroll
    for (int i = 0; i < 8; i++) {
        int v = t + i * 256;
        int row = v >> 4, c = (v & 15) * 4;
        float4 x4 = *reinterpret_cast<const float4*>(&qptr[row * HS + c]);
        float* d = &Qs[row * SQ + c];
        d[0] = f2tff(x4.x * 0.125f); d[1] = f2tff(x4.y * 0.125f);
        d[2] = f2tff(x4.z * 0.125f); d[3] = f2tff(x4.w * 0.125f);
    }

    float m0 = -1e30f, m1 = -1e30f, l0 = 0.f, l1 = 0.f;
    float acc[8][4];
#pragma unroll
    for (int nt = 0; nt < 8; nt++)
#pragma unroll
        for (int j = 0; j < 4; j++) acc[nt][j] = 0.f;

    const float* kptr = kg + bh * HS;
    const float* vptr = vg + bh * HS;
    const int nkb = 2 * qb + 2;
    const int row_w = w * 16 + rg;   // local fragment row (and +8)

    for (int kb = 0; kb < nkb; kb++) {
        __syncthreads();   // K/V reuse barrier (also covers initial Q staging)
#pragma unroll
        for (int i = 0; i < 4; i++) {
            int v = t + i * 256;
            int row = v >> 4, c = (v & 15) * 4;
            float4 k4 = *reinterpret_cast<const float4*>(&kptr[((long long)kb * 64 + row) * HS + c]);
            float* dk = &Ks[row * SK + c];
            dk[0] = f2tff(k4.x); dk[1] = f2tff(k4.y);
            dk[2] = f2tff(k4.z); dk[3] = f2tff(k4.w);
            float4 v4 = *reinterpret_cast<const float4*>(&vptr[((long long)kb * 64 + row) * HS + c]);
            float* dv = &Vs[row * SV + c];
            dv[0] = f2tff(v4.x); dv[1] = f2tff(v4.y);
            dv[2] = f2tff(v4.z); dv[3] = f2tff(v4.w);
        }
        __syncthreads();

        // ---- S = Q @ K^T  (warp tile 16 x 64, K = 64) ----
        float s[8][4];
#pragma unroll
        for (int nt = 0; nt < 8; nt++)
#pragma unroll
            for (int j = 0; j < 4; j++) s[nt][j] = 0.f;

#pragma unroll
        for (int ks = 0; ks < 8; ks++) {
            const float* pa = &Qs[row_w * SQ + ks * 8 + tg];
            uint32_t af[4] = { __float_as_uint(pa[0]), __float_as_uint(pa[8 * SQ]),
                               __float_as_uint(pa[4]), __float_as_uint(pa[8 * SQ + 4]) };
#pragma unroll
            for (int nt = 0; nt < 8; nt++) {
                const float* pb = &Ks[(nt * 8 + rg) * SK + ks * 8 + tg];
                uint32_t bf[2] = { __float_as_uint(pb[0]), __float_as_uint(pb[4]) };
                mma_tf32(s[nt], af, bf);
            }
        }

        // causal mask (only the last two key blocks can clip)
        if (kb >= 2 * qb) {
            int rgl = q0 + row_w;
#pragma unroll
            for (int nt = 0; nt < 8; nt++) {
                int c0 = kb * 64 + nt * 8 + 2 * tg;
                if (c0     > rgl)     s[nt][0] = -1e30f;
                if (c0 + 1 > rgl)     s[nt][1] = -1e30f;
                if (c0     > rgl + 8) s[nt][2] = -1e30f;
                if (c0 + 1 > rgl + 8) s[nt][3] = -1e30f;
            }
        }

        // ---- register online softmax (rows rg, rg+8 per thread; quad reduce) ----
        float vx0 = -1e30f, vx1 = -1e30f;
#pragma unroll
        for (int nt = 0; nt < 8; nt++) {
            vx0 = fmaxf(vx0, fmaxf(s[nt][0], s[nt][1]));
            vx1 = fmaxf(vx1, fmaxf(s[nt][2], s[nt][3]));
        }
        vx0 = fmaxf(vx0, __shfl_xor_sync(0xffffffffu, vx0, 1));
        vx0 = fmaxf(vx0, __shfl_xor_sync(0xffffffffu, vx0, 2));
        vx1 = fmaxf(vx1, __shfl_xor_sync(0xffffffffu, vx1, 1));
        vx1 = fmaxf(vx1, __shfl_xor_sync(0xffffffffu, vx1, 2));

        float mn0 = fmaxf(m0, vx0), mn1 = fmaxf(m1, vx1);
        float al0 = __expf(m0 - mn0), al1 = __expf(m1 - mn1);
        m0 = mn0; m1 = mn1;

        float sum0 = 0.f, sum1 = 0.f;
#pragma unroll
        for (int nt = 0; nt < 8; nt++) {
            float p00 = __expf(s[nt][0] - m0);
            float p01 = __expf(s[nt][1] - m0);
            float p10 = __expf(s[nt][2] - m1);
            float p11 = __expf(s[nt][3] - m1);
            sum0 += p00 + p01;
            sum1 += p10 + p11;
            int cc = nt * 8 + 2 * tg;
            Ps[row_w * SP + cc]           = f2tff(p00);
            Ps[row_w * SP + cc + 1]       = f2tff(p01);
            Ps[(row_w + 8) * SP + cc]     = f2tff(p10);
            Ps[(row_w + 8) * SP + cc + 1] = f2tff(p11);
        }
        sum0 += __shfl_xor_sync(0xffffffffu, sum0, 1);
        sum0 += __shfl_xor_sync(0xffffffffu, sum0, 2);
        sum1 += __shfl_xor_sync(0xffffffffu, sum1, 1);
        sum1 += __shfl_xor_sync(0xffffffffu, sum1, 2);
        l0 = l0 * al0 + sum0;
        l1 = l1 * al1 + sum1;

#pragma unroll
        for (int nt = 0; nt < 8; nt++) {
            acc[nt][0] *= al0; acc[nt][1] *= al0;
            acc[nt][2] *= al1; acc[nt][3] *= al1;
        }
        __syncwarp();

        // ---- PV: acc(16 x 64) += P(16 x 64) @ V(64 x 64) ----
#pragma unroll
        for (int ks = 0; ks < 8; ks++) {
            const float* pa = &Ps[row_w * SP + ks * 8 + tg];
            uint32_t af[4] = { __float_as_uint(pa[0]), __float_as_uint(pa[8 * SP]),
                               __float_as_uint(pa[4]), __float_as_uint(pa[8 * SP + 4]) };
#pragma unroll
            for (int nt = 0; nt < 8; nt++) {
                const float* pb = &Vs[(ks * 8 + tg) * SV + nt * 8 + rg];
                uint32_t bf[2] = { __float_as_uint(pb[0]), __float_as_uint(pb[4 * SV]) };
                mma_tf32(acc[nt], af, bf);
            }
        }
    }

    // ---- epilogue: normalize and write y[b, t, h*64 + d] ----
    float il0 = 1.f / l0, il1 = 1.f / l1;
    float* op = y + ((long long)b * TT + q0 + row_w) * CC + h * HS;
#pragma unroll
    for (int nt = 0; nt < 8; nt++) {
        int cc = nt * 8 + 2 * tg;
        *reinterpret_cast<float2*>(&op[cc]) =
            make_float2(acc[nt][0] * il0, acc[nt][1] * il0);
        *reinterpret_cast<float2*>(&op[(long long)CC * 8 + cc]) =
            make_float2(acc[nt][2] * il1, acc[nt][3] * il1);
    }
}

// ---------------- launch ----------------
extern "C" void kernel_launch(void* const* d_in, const int* in_sizes, int n_in,
                              void* d_out, int out_size)
{
    const float* x     = (const float*)d_in[0];   // (4,2048,1024)
    const float* W_dq  = (const float*)d_in[1];   // (256,1024)
    const float* W_uq  = (const float*)d_in[2];   // (1024,256)
    const float* W_dkv = (const float*)d_in[3];   // (256,1024)
    const float* W_uk  = (const float*)d_in[4];   // (1024,256)
    const float* W_uv  = (const float*)d_in[5];   // (1024,256)
    const float* W_o   = (const float*)d_in[6];   // (1024,1024)

    float* y   = (float*)d_out;                    // (4,2048,1024)
    float* ckv = y + (long long)BB * TT * CC;      // (4,2048,256)

    float *p_tmp1, *p_M, *p_Vt, *p_cq, *p_q, *p_kk, *p_vv;
    cudaGetSymbolAddress((void**)&p_tmp1, g_tmp1);
    cudaGetSymbolAddress((void**)&p_M,    g_M);
    cudaGetSymbolAddress((void**)&p_Vt,   g_Vt);
    cudaGetSymbolAddress((void**)&p_cq,   g_cq);
    cudaGetSymbolAddress((void**)&p_q,    g_q);
    cudaGetSymbolAddress((void**)&p_kk,   g_kk);
    cudaGetSymbolAddress((void**)&p_vv,   g_vv);

    dim3 thr(256);
    const long long HD = (long long)HS * LL;   // 64*256 head-slab stride

    // 1. tmp1[i,j] = sum_c W_uq[c,i] * W_uk[c,j]       (256 x 256, K=1024)
    gemm_tf32<64><<<dim3(4, 2, 1), thr>>>(W_uq, W_uk, p_tmp1,
        256, 256, 1024,  1, 256,  1, 256,  256,
        1, 0, 0, 0, 0, 0, 0);

    // 2. M[c,j] = sum_i W_dq[i,c] * tmp1[i,j]  (k_eff)  (1024 x 256, K=256)
    gemm_tf32<64><<<dim3(4, 8, 1), thr>>>(W_dq, p_tmp1, p_M,
        1024, 256, 256,  1, 1024,  1, 256,  256,
        1, 0, 0, 0, 0, 0, 0);

    // 3. Vt[d,l] = sum_c W_o[d,c] * W_uv[c,l]  (v_eff^T) (1024 x 256, K=1024)
    gemm_tf32<64><<<dim3(4, 8, 1), thr>>>(W_o, W_uv, p_Vt,
        1024, 256, 1024,  1024, 1,  1, 256,  256,
        1, 0, 0, 0, 0, 0, 0);

    // 4. cq = x @ W_dq^T                               (8192 x 256, K=1024)
    gemm_tf32<128><<<dim3(2, 64, 1), thr>>>(x, W_dq, p_cq,
        8192, 256, 1024,  1024, 1,  1024, 1,  256,
        1, 0, 0, 0, 0, 0, 0);

    // 5. c_kv = x @ W_dkv^T -> second output region
    gemm_tf32<128><<<dim3(2, 64, 1), thr>>>(x, W_dkv, ckv,
        8192, 256, 1024,  1024, 1,  1024, 1,  256,
        1, 0, 0, 0, 0, 0, 0);

    // 6. q[b,h] = cq[b] @ W_uq[h*64:+64,:]^T           (64 x 2048 x 64, K=256)
    gemm_tf32<64><<<dim3(1, 16, 64), thr>>>(p_cq, W_uq, p_q,
        2048, 64, 256,  256, 1,  256, 1,  64,
        16, (long long)TT * LL, 0,  0, HD,
        (long long)NH * TT * HS, (long long)TT * HS);

    // 7. KK[b,h] = ckv[b] @ k_eff_h^T = ckv @ M[h*64:+64,:]^T
    gemm_tf32<64><<<dim3(1, 16, 64), thr>>>(ckv, p_M, p_kk,
        2048, 64, 256,  256, 1,  256, 1,  64,
        16, (long long)TT * LL, 0,  0, HD,
        (long long)NH * TT * HS, (long long)TT * HS);

    // 8. VV[b,h] = ckv[b] @ v_eff_h = ckv @ Vt[h*64:+64,:]^T
    gemm_tf32<64><<<dim3(1, 16, 64), thr>>>(ckv, p_Vt, p_vv,
        2048, 64, 256,  256, 1,  256, 1,  64,
        16, (long long)TT * LL, 0,  0, HD,
        (long long)NH * TT * HS, (long long)TT * HS);

    // 9. flash attention (hs=64), writes y head-slices directly
    cudaFuncSetAttribute(flash2, cudaFuncAttributeMaxDynamicSharedMemorySize,
                         FA2_SMEM_BYTES);
    flash2<<<dim3(TT / 128, NH, BB), thr, FA2_SMEM_BYTES>>>(p_q, p_kk, p_vv, y);
}

// round 11
// speedup vs baseline: 16.7649x; 1.3954x over previous
#include <cuda_runtime.h>
#include <cuda_bf16.h>
#include <cstdint>

// Problem dims (fixed per reference)
#define BB   4
#define TT   2048
#define CC   1024
#define NH   16
#define HS   64
#define LL   256

// ---------------- scratch (device globals; no runtime allocation) ----------------
__device__ float g_tmp1[LL * LL];            // W_uq^T @ W_uk            (256,256)
__device__ float g_M[CC * LL];               // W_dq^T @ tmp1 (k_eff)    (1024,256)
__device__ float g_Vt[CC * LL];              // v_eff^T: Vt[d,l]         (1024,256)
__device__ float g_cq[BB * TT * LL];         // x @ W_dq^T               (8192,256)
__device__ float g_qf[(long long)BB * TT * CC];   // q_full  (8192,1024)
__device__ float g_kf[(long long)BB * TT * CC];   // KK_full (8192,1024)
__device__ float g_vf[(long long)BB * TT * CC];   // VV_full (8192,1024)

// ---------------- tf32 helpers ----------------
__device__ __forceinline__ float f2tff(float x) {
    uint32_t r;
    asm("cvt.rna.tf32.f32 %0, %1;" : "=r"(r) : "f"(x));
    return __uint_as_float(r);
}

__device__ __forceinline__ void mma_tf32(float* d, const uint32_t* a, const uint32_t* b) {
    asm volatile(
        "mma.sync.aligned.m16n8k8.row.col.f32.tf32.tf32.f32 "
        "{%0,%1,%2,%3},{%4,%5,%6,%7},{%8,%9},{%0,%1,%2,%3};\n"
        : "+f"(d[0]), "+f"(d[1]), "+f"(d[2]), "+f"(d[3])
        : "r"(a[0]), "r"(a[1]), "r"(a[2]), "r"(a[3]), "r"(b[0]), "r"(b[1]));
}

// ---------------- multi-op TF32 GEMM ----------------
// Up to 4 independent GEMMs in one launch; blockIdx.z selects the op.
// C[m,n] = sum_k A[m*sa_m + k*sa_k] * B[n*sb_n + k*sb_k]
// All ops in a launch share N, K (and BN). Per-op M; oversize y-blocks early-exit.
struct GOps {
    const float* A[4]; const float* B[4]; float* C[4];
    int M[4];
    long long sa_m[4], sa_k[4], sb_n[4], sb_k[4], sc_m[4];
};

template<int BN>
__global__ void __launch_bounds__(256)
gemm_multi(GOps ops, int N, int K)
{
    const int BM = 128, BK = 16, SA = 20, SB = 20;
    const int WN = BN / 2;
    const int NT = WN / 8;
    const int RBS = (BN * BK) / 256;
    const int RBV = RBS / 4;

    const int op = blockIdx.z;
    const int M = ops.M[op];
    const long long bm = (long long)blockIdx.y * BM;
    if (bm >= M) return;                     // oversize y-block for this op

    const float* __restrict__ A = ops.A[op];
    const float* __restrict__ B = ops.B[op];
    float* __restrict__ C = ops.C[op];
    const long long sa_m = ops.sa_m[op], sa_k = ops.sa_k[op];
    const long long sb_n = ops.sb_n[op], sb_k = ops.sb_k[op];
    const long long sc_m = ops.sc_m[op];

    __shared__ float As[2][BM * SA];
    __shared__ float Bs[2][BN * SB];

    const int t = threadIdx.x, lane = t & 31, wid = t >> 5;
    const int warp_m = wid & 3, warp_n = wid >> 2;
    const int rg = lane >> 2;
    const int tg = lane & 3;
    const long long bn = (long long)blockIdx.x * BN;

    const bool vecA = (sa_k == 1), vecB = (sb_k == 1);
    const int nk = K / BK;

    float acc[2][NT][4];
#pragma unroll
    for (int mt = 0; mt < 2; mt++)
#pragma unroll
        for (int nt = 0; nt < NT; nt++)
#pragma unroll
            for (int j = 0; j < 4; j++) acc[mt][nt][j] = 0.f;

    float ra[8], rb[RBS];

    auto loadA = [&](int kt) {
        long long k0 = (long long)kt * BK;
        if (vecA) {
#pragma unroll
            for (int i = 0; i < 2; i++) {
                int f = t + i * 256;
                int row = f >> 2, c4 = (f & 3) * 4;
                float4 v = *reinterpret_cast<const float4*>(&A[(bm + row) * sa_m + k0 + c4]);
                ra[i * 4 + 0] = v.x; ra[i * 4 + 1] = v.y;
                ra[i * 4 + 2] = v.z; ra[i * 4 + 3] = v.w;
            }
        } else {
#pragma unroll
            for (int i = 0; i < 8; i++) {
                int e = t + i * 256;
                int kk = e >> 7, row = e & 127;
                ra[i] = A[(bm + row) * sa_m + (k0 + kk) * sa_k];
            }
        }
    };
    auto storeA = [&](int buf) {
        if (vecA) {
#pragma unroll
            for (int i = 0; i < 2; i++) {
                int f = t + i * 256;
                int row = f >> 2, c4 = (f & 3) * 4;
                float* d = &As[buf][row * SA + c4];
#pragma unroll
                for (int j = 0; j < 4; j++) d[j] = f2tff(ra[i * 4 + j]);
            }
        } else {
#pragma unroll
            for (int i = 0; i < 8; i++) {
                int e = t + i * 256;
                int kk = e >> 7, row = e & 127;
                As[buf][row * SA + kk] = f2tff(ra[i]);
            }
        }
    };
    auto loadB = [&](int kt) {
        long long k0 = (long long)kt * BK;
        if (vecB) {
#pragma unroll
            for (int i = 0; i < RBV; i++) {
                int f = t + i * 256;
                int row = f >> 2, c4 = (f & 3) * 4;
                float4 v = *reinterpret_cast<const float4*>(&B[(bn + row) * sb_n + k0 + c4]);
                rb[i * 4 + 0] = v.x; rb[i * 4 + 1] = v.y;
                rb[i * 4 + 2] = v.z; rb[i * 4 + 3] = v.w;
            }
        } else {
#pragma unroll
            for (int i = 0; i < RBS; i++) {
                int e = t + i * 256;
                int kk = e / BN, n = e % BN;
                rb[i] = B[(bn + n) * sb_n + (k0 + kk) * sb_k];
            }
        }
    };
    auto storeB = [&](int buf) {
        if (vecB) {
#pragma unroll
            for (int i = 0; i < RBV; i++) {
                int f = t + i * 256;
                int row = f >> 2, c4 = (f & 3) * 4;
                float* d = &Bs[buf][row * SB + c4];
#pragma unroll
                for (int j = 0; j < 4; j++) d[j] = f2tff(rb[i * 4 + j]);
            }
        } else {
#pragma unroll
            for (int i = 0; i < RBS; i++) {
                int e = t + i * 256;
                int kk = e / BN, n = e % BN;
                Bs[buf][n * SB + kk] = f2tff(rb[i]);
            }
        }
    };

    auto compute = [&](int buf) {
#pragma unroll
        for (int ks = 0; ks < 2; ks++) {
            uint32_t af[2][4];
            const int ar = warp_m * 32 + rg;
            const int ac = ks * 8 + tg;
#pragma unroll
            for (int mt = 0; mt < 2; mt++) {
                const float* p = &As[buf][(ar + mt * 16) * SA + ac];
                af[mt][0] = __float_as_uint(p[0]);
                af[mt][1] = __float_as_uint(p[8 * SA]);
                af[mt][2] = __float_as_uint(p[4]);
                af[mt][3] = __float_as_uint(p[8 * SA + 4]);
            }
            uint32_t bf[NT][2];
            const int br = warp_n * WN + rg;
            const int bc = ks * 8 + tg;
#pragma unroll
            for (int nt = 0; nt < NT; nt++) {
                const float* p = &Bs[buf][(br + nt * 8) * SB + bc];
                bf[nt][0] = __float_as_uint(p[0]);
                bf[nt][1] = __float_as_uint(p[4]);
            }
#pragma unroll
            for (int mt = 0; mt < 2; mt++)
#pragma unroll
                for (int nt = 0; nt < NT; nt++)
                    mma_tf32(acc[mt][nt], af[mt], bf[nt]);
        }
    };

    loadA(0); loadB(0);
    storeA(0); storeB(0);
    __syncthreads();

    for (int kt = 0; kt < nk; kt++) {
        int buf = kt & 1;
        bool nxt = (kt + 1 < nk);
        if (nxt) { loadA(kt + 1); loadB(kt + 1); }
        compute(buf);
        if (nxt) { storeA(buf ^ 1); storeB(buf ^ 1); }
        __syncthreads();
    }

#pragma unroll
    for (int mt = 0; mt < 2; mt++) {
        long long gm0 = bm + warp_m * 32 + mt * 16 + rg;
#pragma unroll
        for (int nt = 0; nt < NT; nt++) {
            long long gn = bn + warp_n * WN + nt * 8 + tg * 2;
            float2 v0 = make_float2(acc[mt][nt][0], acc[mt][nt][1]);
            float2 v1 = make_float2(acc[mt][nt][2], acc[mt][nt][3]);
            *reinterpret_cast<float2*>(&C[gm0 * sc_m + gn]) = v0;
            *reinterpret_cast<float2*>(&C[(gm0 + 8) * sc_m + gn]) = v1;
        }
    }
}

// ---------------- TF32 flash attention, hs = 64 ----------------
// grid = (T/128, NH, B), 256 threads (8 warps). Warp w owns rows 16w..16w+15
// end-to-end: S mma -> register softmax (quad shuffles) -> P via smem -> PV mma.
// q/k/v live in full-width (B,T,NH*HS) layouts; rows have stride CC.
#define SQ 68
#define SK 68
#define SV 72
#define SP 68

#define FA2_SMEM_BYTES ((128 * SQ + 64 * SK + 64 * SV + 128 * SP) * 4)

__global__ void __launch_bounds__(256)
flash2(const float* __restrict__ qg, const float* __restrict__ kg,
       const float* __restrict__ vg, float* __restrict__ y)
{
    extern __shared__ float sh[];
    float* Qs = sh;               // 128 x SQ
    float* Ks = Qs + 128 * SQ;    // 64 x SK
    float* Vs = Ks + 64 * SK;     // 64 x SV
    float* Ps = Vs + 64 * SV;     // 128 x SP

    const int qb = (int)gridDim.x - 1 - (int)blockIdx.x;  // heavy blocks first
    const int h = blockIdx.y, b = blockIdx.z;
    const int t = threadIdx.x, lane = t & 31, w = t >> 5;
    const int rg = lane >> 2, tg = lane & 3;
    const int q0 = qb * 128;

    // stage Q (128 x 64), pre-scaled by 1/sqrt(hs)
    const float* qptr = qg + ((long long)b * TT + q0) * CC + h * HS;
#pragma unroll
    for (int i = 0; i < 8; i++) {
        int v = t + i * 256;
        int row = v >> 4, c = (v & 15) * 4;
        float4 x4 = *reinterpret_cast<const float4*>(&qptr[(long long)row * CC + c]);
        float* d = &Qs[row * SQ + c];
        d[0] = f2tff(x4.x * 0.125f); d[1] = f2tff(x4.y * 0.125f);
        d[2] = f2tff(x4.z * 0.125f); d[3] = f2tff(x4.w * 0.125f);
    }

    float m0 = -1e30f, m1 = -1e30f, l0 = 0.f, l1 = 0.f;
    float acc[8][4];
#pragma unroll
    for (int nt = 0; nt < 8; nt++)
#pragma unroll
        for (int j = 0; j < 4; j++) acc[nt][j] = 0.f;

    const float* kptr = kg + (long long)b * TT * CC + h * HS;
    const float* vptr = vg + (long long)b * TT * CC + h * HS;
    const int nkb = 2 * qb + 2;
    const int row_w = w * 16 + rg;

    for (int kb = 0; kb < nkb; kb++) {
        __syncthreads();   // K/V reuse barrier (also covers initial Q staging)
#pragma unroll
        for (int i = 0; i < 4; i++) {
            int v = t + i * 256;
            int row = v >> 4, c = (v & 15) * 4;
            float4 k4 = *reinterpret_cast<const float4*>(
                &kptr[((long long)kb * 64 + row) * CC + c]);
            float* dk = &Ks[row * SK + c];
            dk[0] = f2tff(k4.x); dk[1] = f2tff(k4.y);
            dk[2] = f2tff(k4.z); dk[3] = f2tff(k4.w);
            float4 v4 = *reinterpret_cast<const float4*>(
                &vptr[((long long)kb * 64 + row) * CC + c]);
            float* dv = &Vs[row * SV + c];
            dv[0] = f2tff(v4.x); dv[1] = f2tff(v4.y);
            dv[2] = f2tff(v4.z); dv[3] = f2tff(v4.w);
        }
        __syncthreads();

        // ---- S = Q @ K^T  (warp tile 16 x 64, K = 64) ----
        float s[8][4];
#pragma unroll
        for (int nt = 0; nt < 8; nt++)
#pragma unroll
            for (int j = 0; j < 4; j++) s[nt][j] = 0.f;

#pragma unroll
        for (int ks = 0; ks < 8; ks++) {
            const float* pa = &Qs[row_w * SQ + ks * 8 + tg];
            uint32_t af[4] = { __float_as_uint(pa[0]), __float_as_uint(pa[8 * SQ]),
                               __float_as_uint(pa[4]), __float_as_uint(pa[8 * SQ + 4]) };
#pragma unroll
            for (int nt = 0; nt < 8; nt++) {
                const float* pb = &Ks[(nt * 8 + rg) * SK + ks * 8 + tg];
                uint32_t bf[2] = { __float_as_uint(pb[0]), __float_as_uint(pb[4]) };
                mma_tf32(s[nt], af, bf);
            }
        }

        // causal mask (only the last two key blocks can clip)
        if (kb >= 2 * qb) {
            int rgl = q0 + row_w;
#pragma unroll
            for (int nt = 0; nt < 8; nt++) {
                int c0 = kb * 64 + nt * 8 + 2 * tg;
                if (c0     > rgl)     s[nt][0] = -1e30f;
                if (c0 + 1 > rgl)     s[nt][1] = -1e30f;
                if (c0     > rgl + 8) s[nt][2] = -1e30f;
                if (c0 + 1 > rgl + 8) s[nt][3] = -1e30f;
            }
        }

        // ---- register online softmax (rows rg, rg+8 per thread; quad reduce) ----
        float vx0 = -1e30f, vx1 = -1e30f;
#pragma unroll
        for (int nt = 0; nt < 8; nt++) {
            vx0 = fmaxf(vx0, fmaxf(s[nt][0], s[nt][1]));
            vx1 = fmaxf(vx1, fmaxf(s[nt][2], s[nt][3]));
        }
        vx0 = fmaxf(vx0, __shfl_xor_sync(0xffffffffu, vx0, 1));
        vx0 = fmaxf(vx0, __shfl_xor_sync(0xffffffffu, vx0, 2));
        vx1 = fmaxf(vx1, __shfl_xor_sync(0xffffffffu, vx1, 1));
        vx1 = fmaxf(vx1, __shfl_xor_sync(0xffffffffu, vx1, 2));

        float mn0 = fmaxf(m0, vx0), mn1 = fmaxf(m1, vx1);
        float al0 = __expf(m0 - mn0), al1 = __expf(m1 - mn1);
        m0 = mn0; m1 = mn1;

        float sum0 = 0.f, sum1 = 0.f;
#pragma unroll
        for (int nt = 0; nt < 8; nt++) {
            float p00 = __expf(s[nt][0] - m0);
            float p01 = __expf(s[nt][1] - m0);
            float p10 = __expf(s[nt][2] - m1);
            float p11 = __expf(s[nt][3] - m1);
            sum0 += p00 + p01;
            sum1 += p10 + p11;
            int cc = nt * 8 + 2 * tg;
            Ps[row_w * SP + cc]           = f2tff(p00);
            Ps[row_w * SP + cc + 1]       = f2tff(p01);
            Ps[(row_w + 8) * SP + cc]     = f2tff(p10);
            Ps[(row_w + 8) * SP + cc + 1] = f2tff(p11);
        }
        sum0 += __shfl_xor_sync(0xffffffffu, sum0, 1);
        sum0 += __shfl_xor_sync(0xffffffffu, sum0, 2);
        sum1 += __shfl_xor_sync(0xffffffffu, sum1, 1);
        sum1 += __shfl_xor_sync(0xffffffffu, sum1, 2);
        l0 = l0 * al0 + sum0;
        l1 = l1 * al1 + sum1;

#pragma unroll
        for (int nt = 0; nt < 8; nt++) {
            acc[nt][0] *= al0; acc[nt][1] *= al0;
            acc[nt][2] *= al1; acc[nt][3] *= al1;
        }
        __syncwarp();

        // ---- PV: acc(16 x 64) += P(16 x 64) @ V(64 x 64) ----
#pragma unroll
        for (int ks = 0; ks < 8; ks++) {
            const float* pa = &Ps[row_w * SP + ks * 8 + tg];
            uint32_t af[4] = { __float_as_uint(pa[0]), __float_as_uint(pa[8 * SP]),
                               __float_as_uint(pa[4]), __float_as_uint(pa[8 * SP + 4]) };
#pragma unroll
            for (int nt = 0; nt < 8; nt++) {
                const float* pb = &Vs[(ks * 8 + tg) * SV + nt * 8 + rg];
                uint32_t bf[2] = { __float_as_uint(pb[0]), __float_as_uint(pb[4 * SV]) };
                mma_tf32(acc[nt], af, bf);
            }
        }
    }

    // ---- epilogue: normalize and write y[b, t, h*64 + d] ----
    float il0 = 1.f / l0, il1 = 1.f / l1;
    float* op = y + ((long long)b * TT + q0 + row_w) * CC + h * HS;
#pragma unroll
    for (int nt = 0; nt < 8; nt++) {
        int cc = nt * 8 + 2 * tg;
        *reinterpret_cast<float2*>(&op[cc]) =
            make_float2(acc[nt][0] * il0, acc[nt][1] * il0);
        *reinterpret_cast<float2*>(&op[(long long)CC * 8 + cc]) =
            make_float2(acc[nt][2] * il1, acc[nt][3] * il1);
    }
}

// ---------------- launch ----------------
extern "C" void kernel_launch(void* const* d_in, const int* in_sizes, int n_in,
                              void* d_out, int out_size)
{
    const float* x     = (const float*)d_in[0];   // (4,2048,1024)
    const float* W_dq  = (const float*)d_in[1];   // (256,1024)
    const float* W_uq  = (const float*)d_in[2];   // (1024,256)
    const float* W_dkv = (const float*)d_in[3];   // (256,1024)
    const float* W_uk  = (const float*)d_in[4];   // (1024,256)
    const float* W_uv  = (const float*)d_in[5];   // (1024,256)
    const float* W_o   = (const float*)d_in[6];   // (1024,1024)

    float* y   = (float*)d_out;                    // (4,2048,1024)
    float* ckv = y + (long long)BB * TT * CC;      // (4,2048,256)

    float *p_tmp1, *p_M, *p_Vt, *p_cq, *p_qf, *p_kf, *p_vf;
    cudaGetSymbolAddress((void**)&p_tmp1, g_tmp1);
    cudaGetSymbolAddress((void**)&p_M,    g_M);
    cudaGetSymbolAddress((void**)&p_Vt,   g_Vt);
    cudaGetSymbolAddress((void**)&p_cq,   g_cq);
    cudaGetSymbolAddress((void**)&p_qf,   g_qf);
    cudaGetSymbolAddress((void**)&p_kf,   g_kf);
    cudaGetSymbolAddress((void**)&p_vf,   g_vf);

    dim3 thr(256);

    // ---- Launch C: 4 independent ops, N=256, K=1024 ----
    //  op0: cq   = x @ W_dq^T                       (8192 x 256)
    //  op1: ckv  = x @ W_dkv^T   -> output region   (8192 x 256)
    //  op2: Vt[d,l] = sum_c W_o[d,c] W_uv[c,l]      (1024 x 256)
    //  op3: tmp1[i,j] = sum_c W_uq[c,i] W_uk[c,j]   ( 256 x 256)
    {
        GOps o = {};
        o.A[0] = x;     o.B[0] = W_dq;  o.C[0] = p_cq;   o.M[0] = 8192;
        o.sa_m[0] = 1024; o.sa_k[0] = 1; o.sb_n[0] = 1024; o.sb_k[0] = 1; o.sc_m[0] = 256;
        o.A[1] = x;     o.B[1] = W_dkv; o.C[1] = ckv;    o.M[1] = 8192;
        o.sa_m[1] = 1024; o.sa_k[1] = 1; o.sb_n[1] = 1024; o.sb_k[1] = 1; o.sc_m[1] = 256;
        o.A[2] = W_o;   o.B[2] = W_uv;  o.C[2] = p_Vt;   o.M[2] = 1024;
        o.sa_m[2] = 1024; o.sa_k[2] = 1; o.sb_n[2] = 1;    o.sb_k[2] = 256; o.sc_m[2] = 256;
        o.A[3] = W_uq;  o.B[3] = W_uk;  o.C[3] = p_tmp1; o.M[3] = 256;
        o.sa_m[3] = 1;  o.sa_k[3] = 256; o.sb_n[3] = 1;   o.sb_k[3] = 256; o.sc_m[3] = 256;
        gemm_multi<128><<<dim3(2, 64, 4), thr>>>(o, 256, 1024);
    }

    // ---- Launch B: M[c,j] = sum_i W_dq[i,c] tmp1[i,j]   (1024 x 256, K=256) ----
    {
        GOps o = {};
        o.A[0] = W_dq; o.B[0] = p_tmp1; o.C[0] = p_M; o.M[0] = 1024;
        o.sa_m[0] = 1; o.sa_k[0] = 1024; o.sb_n[0] = 1; o.sb_k[0] = 256; o.sc_m[0] = 256;
        gemm_multi<128><<<dim3(2, 8, 1), thr>>>(o, 256, 256);
    }

    // ---- Launch D: 3 full-width head GEMMs, M=8192, N=1024, K=256 ----
    //  op0: q_full  = cq  @ W_uq^T
    //  op1: KK_full = ckv @ M^T
    //  op2: VV_full = ckv @ Vt^T
    {
        GOps o = {};
        o.A[0] = p_cq; o.B[0] = W_uq; o.C[0] = p_qf; o.M[0] = 8192;
        o.sa_m[0] = 256; o.sa_k[0] = 1; o.sb_n[0] = 256; o.sb_k[0] = 1; o.sc_m[0] = 1024;
        o.A[1] = ckv;  o.B[1] = p_M;  o.C[1] = p_kf; o.M[1] = 8192;
        o.sa_m[1] = 256; o.sa_k[1] = 1; o.sb_n[1] = 256; o.sb_k[1] = 1; o.sc_m[1] = 1024;
        o.A[2] = ckv;  o.B[2] = p_Vt; o.C[2] = p_vf; o.M[2] = 8192;
        o.sa_m[2] = 256; o.sa_k[2] = 1; o.sb_n[2] = 256; o.sb_k[2] = 1; o.sc_m[2] = 1024;
        gemm_multi<128><<<dim3(8, 64, 3), thr>>>(o, 1024, 256);
    }

    // ---- flash attention (hs=64), writes y head-slices directly ----
    cudaFuncSetAttribute(flash2, cudaFuncAttributeMaxDynamicSharedMemorySize,
                         FA2_SMEM_BYTES);
    flash2<<<dim3(TT / 128, NH, BB), thr, FA2_SMEM_BYTES>>>(p_qf, p_kf, p_vf, y);
}